// round 3
// baseline (speedup 1.0000x reference)
#include <cuda_runtime.h>
#include <math.h>

#define BB 64
#define SS 512
#define FF 512
#define HH 1024
#define G3 3072
#define NBLOCKS 128
#define HP 1025          // smem h-tile row pitch (odd => conflict-free strided LDS)

// Scratch for input-side gates gx = x @ W_ih + bias : [B*S, 3H] fp32 (402 MB)
__device__ float g_gx[(size_t)BB * SS * G3];

// Software grid barrier state (generation counter needs no per-launch reset)
__device__ unsigned int g_count = 0;
__device__ volatile unsigned int g_gen = 0;

__device__ __forceinline__ float gate_fn(float az, float ar, float ge, float ae, float ho) {
    float z   = 1.0f / (1.0f + expf(-az));
    float r   = 1.0f / (1.0f + expf(-ar));
    float eta = tanhf(ge + r * tanhf(ae));
    return z * ho + (1.0f - z) * eta;
}

// ---------------------------------------------------------------------------
// Kernel 1: input GEMM  g_gx[m][n] = sum_k x[m][k]*wih[k][n] + bias[n]
//   M = B*S = 32768, K = 512, N = 3072.  128x128x16 tiles, 8x8 per thread.
// ---------------------------------------------------------------------------
__global__ __launch_bounds__(256) void gemm_ih(const float* __restrict__ A,
                                               const float* __restrict__ Bw,
                                               const float* __restrict__ bias) {
    __shared__ float As[16][132];   // transposed A tile [k][m], padded
    __shared__ float Bs[16][128];   // B tile [k][n]

    const int K = FF, N = G3;
    const int bm = blockIdx.y * 128;
    const int bn = blockIdx.x * 128;
    const int tid = threadIdx.x;
    const int tr = tid >> 4;        // 0..15 row-block
    const int tc = tid & 15;        // 0..15 col-block

    float acc[8][8];
#pragma unroll
    for (int i = 0; i < 8; ++i)
#pragma unroll
        for (int j = 0; j < 8; ++j) acc[i][j] = 0.0f;

    for (int k0 = 0; k0 < K; k0 += 16) {
#pragma unroll
        for (int i = 0; i < 2; ++i) {
            int f = tid + i * 256;            // 0..511
            // A tile: 128 rows x 16 cols = 512 float4
            int ar = f >> 2, ac4 = f & 3;
            float4 av = *(const float4*)(A + (size_t)(bm + ar) * K + k0 + ac4 * 4);
            As[ac4 * 4 + 0][ar] = av.x;
            As[ac4 * 4 + 1][ar] = av.y;
            As[ac4 * 4 + 2][ar] = av.z;
            As[ac4 * 4 + 3][ar] = av.w;
            // B tile: 16 rows x 128 cols = 512 float4
            int br = f >> 5, bc4 = f & 31;
            *(float4*)(&Bs[br][bc4 * 4]) =
                *(const float4*)(Bw + (size_t)(k0 + br) * N + bn + bc4 * 4);
        }
        __syncthreads();
#pragma unroll
        for (int kk = 0; kk < 16; ++kk) {
            float a[8], b[8];
            *(float4*)(a)     = *(const float4*)(&As[kk][tr * 8]);
            *(float4*)(a + 4) = *(const float4*)(&As[kk][tr * 8 + 4]);
            *(float4*)(b)     = *(const float4*)(&Bs[kk][tc * 8]);
            *(float4*)(b + 4) = *(const float4*)(&Bs[kk][tc * 8 + 4]);
#pragma unroll
            for (int i = 0; i < 8; ++i)
#pragma unroll
                for (int j = 0; j < 8; ++j) acc[i][j] += a[i] * b[j];
        }
        __syncthreads();
    }

#pragma unroll
    for (int i = 0; i < 8; ++i) {
        int row = bm + tr * 8 + i;
#pragma unroll
        for (int j = 0; j < 8; j += 4) {
            int col = bn + tc * 8 + j;
            float4 bv = *(const float4*)(bias + col);
            float4 o;
            o.x = acc[i][j + 0] + bv.x;
            o.y = acc[i][j + 1] + bv.y;
            o.z = acc[i][j + 2] + bv.z;
            o.w = acc[i][j + 3] + bv.w;
            *(float4*)(g_gx + (size_t)row * N + col) = o;
        }
    }
}

// ---------------------------------------------------------------------------
// Kernel 2: persistent GRU scan. 128 CTAs (1/SM, all resident), 512 steps.
//   CTA (mt,jt): batch rows [32*mt, +32), hidden cols [16*jt, +16).
//   Per step: gh = h_{t-1} @ W_hh (K split 4-way across thread groups),
//   fused gates, h_t written to out[:, t, :], then grid-wide barrier.
// ---------------------------------------------------------------------------
__global__ __launch_bounds__(256, 1) void gru_scan(const float* __restrict__ whh,
                                                   float* out) {
    extern __shared__ float smem[];
    float* hsm = smem;                                   // [32][HP]
    float4* scrf4 = (float4*)(smem + 32 * HP);           // [3][64][6] float4

    const int bid = blockIdx.x;
    const int mt = bid >> 6;            // 0..1
    const int jt = bid & 63;            // 0..63
    const int m0 = mt * 32;
    const int jbase = jt * 16;
    const int tid = threadIdx.x;
    const int kq = tid >> 6;            // K-quarter 0..3
    const int local = tid & 63;
    const int mp = local & 15;          // rows 2mp, 2mp+1 (local)
    const int jq = local >> 4;          // 0..3
    const int j0 = jbase + 4 * jq;      // 4 consecutive hidden cols

    for (int t = 0; t < SS; ++t) {
        float4 a0z = {0, 0, 0, 0}, a0r = a0z, a0e = a0z;
        float4 a1z = a0z, a1r = a0z, a1e = a0z;

        if (t > 0) {
            // cooperative load of h_{t-1} tile [32 x 1024] into smem (coalesced)
#pragma unroll 4
            for (int i = tid; i < 32 * HH; i += 256) {
                int r = i >> 10, k = i & 1023;
                hsm[r * HP + k] = out[((size_t)(m0 + r) * SS + (t - 1)) * HH + k];
            }
            __syncthreads();

            const float* h0p = hsm + (2 * mp) * HP + kq * 256;
            const float* h1p = h0p + HP;
            const float* wp = whh + (size_t)(kq * 256) * G3 + j0;
#pragma unroll 4
            for (int k = 0; k < 256; ++k) {
                float4 wz = *(const float4*)(wp);
                float4 wr = *(const float4*)(wp + HH);
                float4 we = *(const float4*)(wp + 2 * HH);
                float h0 = h0p[k];
                float h1 = h1p[k];
                a0z.x += h0 * wz.x; a0z.y += h0 * wz.y; a0z.z += h0 * wz.z; a0z.w += h0 * wz.w;
                a0r.x += h0 * wr.x; a0r.y += h0 * wr.y; a0r.z += h0 * wr.z; a0r.w += h0 * wr.w;
                a0e.x += h0 * we.x; a0e.y += h0 * we.y; a0e.z += h0 * we.z; a0e.w += h0 * we.w;
                a1z.x += h1 * wz.x; a1z.y += h1 * wz.y; a1z.z += h1 * wz.z; a1z.w += h1 * wz.w;
                a1r.x += h1 * wr.x; a1r.y += h1 * wr.y; a1r.z += h1 * wr.z; a1r.w += h1 * wr.w;
                a1e.x += h1 * we.x; a1e.y += h1 * we.y; a1e.z += h1 * we.z; a1e.w += h1 * we.w;
                wp += G3;
            }
            if (kq > 0) {
                float4* s = scrf4 + ((size_t)(kq - 1) * 64 + local) * 6;
                s[0] = a0z; s[1] = a0r; s[2] = a0e;
                s[3] = a1z; s[4] = a1r; s[5] = a1e;
            }
        }
        __syncthreads();

        if (kq == 0) {
            float ho0[4] = {0, 0, 0, 0}, ho1[4] = {0, 0, 0, 0};
            if (t > 0) {
#pragma unroll
                for (int q = 0; q < 3; ++q) {
                    const float4* s = scrf4 + ((size_t)q * 64 + local) * 6;
                    float4 v;
                    v = s[0]; a0z.x += v.x; a0z.y += v.y; a0z.z += v.z; a0z.w += v.w;
                    v = s[1]; a0r.x += v.x; a0r.y += v.y; a0r.z += v.z; a0r.w += v.w;
                    v = s[2]; a0e.x += v.x; a0e.y += v.y; a0e.z += v.z; a0e.w += v.w;
                    v = s[3]; a1z.x += v.x; a1z.y += v.y; a1z.z += v.z; a1z.w += v.w;
                    v = s[4]; a1r.x += v.x; a1r.y += v.y; a1r.z += v.z; a1r.w += v.w;
                    v = s[5]; a1e.x += v.x; a1e.y += v.y; a1e.z += v.z; a1e.w += v.w;
                }
#pragma unroll
                for (int c = 0; c < 4; ++c) {
                    ho0[c] = hsm[(2 * mp) * HP + j0 + c];
                    ho1[c] = hsm[(2 * mp + 1) * HP + j0 + c];
                }
            }
            int b0 = m0 + 2 * mp;
            const float* gp0 = g_gx + ((size_t)b0 * SS + t) * G3 + j0;
            const float* gp1 = gp0 + (size_t)SS * G3;
            float4 gz0 = *(const float4*)(gp0);
            float4 gr0 = *(const float4*)(gp0 + HH);
            float4 ge0 = *(const float4*)(gp0 + 2 * HH);
            float4 gz1 = *(const float4*)(gp1);
            float4 gr1 = *(const float4*)(gp1 + HH);
            float4 ge1 = *(const float4*)(gp1 + 2 * HH);
            float4 hn0, hn1;
            hn0.x = gate_fn(gz0.x + a0z.x, gr0.x + a0r.x, ge0.x, a0e.x, ho0[0]);
            hn0.y = gate_fn(gz0.y + a0z.y, gr0.y + a0r.y, ge0.y, a0e.y, ho0[1]);
            hn0.z = gate_fn(gz0.z + a0z.z, gr0.z + a0r.z, ge0.z, a0e.z, ho0[2]);
            hn0.w = gate_fn(gz0.w + a0z.w, gr0.w + a0r.w, ge0.w, a0e.w, ho0[3]);
            hn1.x = gate_fn(gz1.x + a1z.x, gr1.x + a1r.x, ge1.x, a1e.x, ho1[0]);
            hn1.y = gate_fn(gz1.y + a1z.y, gr1.y + a1r.y, ge1.y, a1e.y, ho1[1]);
            hn1.z = gate_fn(gz1.z + a1z.z, gr1.z + a1r.z, ge1.z, a1e.z, ho1[2]);
            hn1.w = gate_fn(gz1.w + a1z.w, gr1.w + a1r.w, ge1.w, a1e.w, ho1[3]);
            *(float4*)(out + ((size_t)b0 * SS + t) * HH + j0) = hn0;
            *(float4*)(out + ((size_t)(b0 + 1) * SS + t) * HH + j0) = hn1;
        }

        // ---- grid-wide barrier (generation counter, replay-safe) ----
        __syncthreads();
        if (tid == 0) {
            __threadfence();
            unsigned int my = g_gen;
            unsigned int old = atomicAdd(&g_count, 1u);
            if (old == NBLOCKS - 1) {
                atomicExch(&g_count, 0u);
                __threadfence();
                g_gen = my + 1u;
            } else {
                while (g_gen == my) { __nanosleep(64); }
            }
            __threadfence();
        }
        __syncthreads();
    }

    // h_last = hidden_seq[:, S-1, :], appended after hidden_seq
    {
        size_t base = (size_t)bid * 512;
        for (int i = tid; i < 512; i += 256) {
            size_t idx = base + i;                 // 0..65535
            int b = (int)(idx >> 10);
            int jx = (int)(idx & 1023);
            out[(size_t)BB * SS * HH + idx] =
                out[((size_t)b * SS + (SS - 1)) * HH + jx];
        }
    }
}

// ---------------------------------------------------------------------------
extern "C" void kernel_launch(void* const* d_in, const int* in_sizes, int n_in,
                              void* d_out, int out_size) {
    const float* x    = (const float*)d_in[0];  // [64,512,512]
    const float* wih  = (const float*)d_in[1];  // [512,3072]
    const float* whh  = (const float*)d_in[2];  // [1024,3072]
    const float* bias = (const float*)d_in[3];  // [3072]
    float* out = (float*)d_out;                 // [64*512*1024 + 64*1024]

    (void)in_sizes; (void)n_in; (void)out_size;

    // Phase 1: gx = x @ W_ih + bias
    dim3 g1(G3 / 128, (BB * SS) / 128);
    gemm_ih<<<g1, 256>>>(x, wih, bias);

    // Phase 2: persistent sequential scan
    const int scan_smem = (32 * HP + 3 * 64 * 6 * 4) * (int)sizeof(float); // ~149.6 KB
    cudaFuncSetAttribute(gru_scan, cudaFuncAttributeMaxDynamicSharedMemorySize, scan_smem);
    gru_scan<<<NBLOCKS, 256, scan_smem>>>(whh, out);
}

// round 4
// speedup vs baseline: 1.5006x; 1.5006x over previous
#include <cuda_runtime.h>
#include <math.h>

#define BB 64
#define SS 512
#define FF 512
#define HH 1024
#define G3 3072
#define NBLOCKS 128
#define NT 512
#define HP 1028            // h-tile pitch: 16B-aligned rows, tolerable LDS conflicts
#define WBUFB 24576        // bytes per W stage buffer (1536 x 16B)
#define SCR_STRIDE 26      // reduction scratch stride (floats): 2-way max conflict, 8B aligned

// Scratch for input-side gates gx = x @ W_ih + bias : [B*S, 3H] fp32
__device__ float g_gx[(size_t)BB * SS * G3];

// Software grid barrier (generation counter — replay-safe, no reset needed)
__device__ unsigned int g_count = 0;
__device__ volatile unsigned int g_gen = 0;

typedef unsigned long long u64t;

// ---------------- f32x2 packed-FMA helpers (Blackwell) ----------------
__device__ __forceinline__ u64t pack2(float lo, float hi) {
    u64t r; asm("mov.b64 %0, {%1, %2};" : "=l"(r) : "f"(lo), "f"(hi)); return r;
}
__device__ __forceinline__ void unpack2(u64t v, float& lo, float& hi) {
    asm("mov.b64 {%0, %1}, %2;" : "=f"(lo), "=f"(hi) : "l"(v));
}
__device__ __forceinline__ void fma2(u64t& d, u64t a, u64t b) {
    asm("fma.rn.f32x2 %0, %1, %2, %0;" : "+l"(d) : "l"(a), "l"(b));
}

// ---------------- cp.async helpers ----------------
__device__ __forceinline__ void cp16(unsigned int dst, const void* src) {
    asm volatile("cp.async.ca.shared.global [%0], [%1], 16;" :: "r"(dst), "l"(src) : "memory");
}
__device__ __forceinline__ void cp_commit() { asm volatile("cp.async.commit_group;" ::: "memory"); }
template<int N> __device__ __forceinline__ void cp_wait() {
    asm volatile("cp.async.wait_group %0;" :: "n"(N) : "memory");
}
__device__ __forceinline__ unsigned int smem_u32(const void* p) {
    return (unsigned int)__cvta_generic_to_shared(p);
}

__device__ __forceinline__ float gate_fn(float az, float ar, float ge, float ae, float ho) {
    float z   = 1.0f / (1.0f + expf(-az));
    float r   = 1.0f / (1.0f + expf(-ar));
    float eta = tanhf(ge + r * tanhf(ae));
    return z * ho + (1.0f - z) * eta;
}

// ---------------------------------------------------------------------------
// Kernel 1: input GEMM  g_gx = x @ W_ih + bias.  M=32768, K=512, N=3072.
//   128x128x16 tiles, 8x8 per thread, f32x2 packed FMA.
// ---------------------------------------------------------------------------
__global__ __launch_bounds__(256, 2) void gemm_ih(const float* __restrict__ A,
                                                  const float* __restrict__ Bw,
                                                  const float* __restrict__ bias) {
    __shared__ float As[16][132];
    __shared__ float Bs[16][128];

    const int K = FF, N = G3;
    const int bm = blockIdx.y * 128;
    const int bn = blockIdx.x * 128;
    const int tid = threadIdx.x;
    const int tr = tid >> 4;
    const int tc = tid & 15;

    u64t acc2[8][4];
#pragma unroll
    for (int i = 0; i < 8; ++i)
#pragma unroll
        for (int j = 0; j < 4; ++j) acc2[i][j] = 0ULL;

    for (int k0 = 0; k0 < K; k0 += 16) {
#pragma unroll
        for (int i = 0; i < 2; ++i) {
            int f = tid + i * 256;
            int ar = f >> 2, ac4 = f & 3;
            float4 av = *(const float4*)(A + (size_t)(bm + ar) * K + k0 + ac4 * 4);
            As[ac4 * 4 + 0][ar] = av.x;
            As[ac4 * 4 + 1][ar] = av.y;
            As[ac4 * 4 + 2][ar] = av.z;
            As[ac4 * 4 + 3][ar] = av.w;
            int br = f >> 5, bc4 = f & 31;
            *(float4*)(&Bs[br][bc4 * 4]) =
                *(const float4*)(Bw + (size_t)(k0 + br) * N + bn + bc4 * 4);
        }
        __syncthreads();
#pragma unroll
        for (int kk = 0; kk < 16; ++kk) {
            float a[8];
            *(float4*)(a)     = *(const float4*)(&As[kk][tr * 8]);
            *(float4*)(a + 4) = *(const float4*)(&As[kk][tr * 8 + 4]);
            ulonglong2 bq0 = *(const ulonglong2*)(&Bs[kk][tc * 8]);
            ulonglong2 bq1 = *(const ulonglong2*)(&Bs[kk][tc * 8 + 4]);
            u64t bp0 = bq0.x, bp1 = bq0.y, bp2 = bq1.x, bp3 = bq1.y;
#pragma unroll
            for (int i = 0; i < 8; ++i) {
                u64t ai = pack2(a[i], a[i]);
                fma2(acc2[i][0], ai, bp0);
                fma2(acc2[i][1], ai, bp1);
                fma2(acc2[i][2], ai, bp2);
                fma2(acc2[i][3], ai, bp3);
            }
        }
        __syncthreads();
    }

#pragma unroll
    for (int i = 0; i < 8; ++i) {
        int row = bm + tr * 8 + i;
        float o[8];
        unpack2(acc2[i][0], o[0], o[1]);
        unpack2(acc2[i][1], o[2], o[3]);
        unpack2(acc2[i][2], o[4], o[5]);
        unpack2(acc2[i][3], o[6], o[7]);
#pragma unroll
        for (int j = 0; j < 8; j += 4) {
            int col = bn + tc * 8 + j;
            float4 bv = *(const float4*)(bias + col);
            float4 ov;
            ov.x = o[j + 0] + bv.x;
            ov.y = o[j + 1] + bv.y;
            ov.z = o[j + 2] + bv.z;
            ov.w = o[j + 3] + bv.w;
            *(float4*)(g_gx + (size_t)row * N + col) = ov;
        }
    }
}

// ---------------------------------------------------------------------------
// Kernel 2: persistent GRU scan. 128 CTAs x 512 threads, 512 steps.
//   CTA (mt,jt): 32 batch rows x 16 hidden cols (48 gate cols).
//   W_hh tile cp.async double-buffered in smem; h tile cp.async staged;
//   8-way K split, f32x2 FMA; gate phase parallel over all 512 threads.
// ---------------------------------------------------------------------------
__global__ __launch_bounds__(NT, 1) void gru_scan(const float* __restrict__ whh,
                                                  float* __restrict__ out) {
    extern __shared__ float smem[];
    float* hsm = smem;                         // [32][HP]
    float* wst = smem + 32 * HP;               // W stage (2 x 6144 fl) / scratch union

    const int bid = blockIdx.x;
    const int mt = bid >> 6;
    const int jt = bid & 63;
    const int m0 = mt * 32;
    const int jbase = jt * 16;
    const int tid = threadIdx.x;
    const int kq = tid >> 6;                   // 0..7 K-octant (128 k each)
    const int local = tid & 63;
    const int mp = local & 15;                 // row-pair
    const int jq = local >> 4;                 // 0..3 col-quad

    // W staging chunk map: 3 x 16B chunks per thread per block
    int widx[3];
    size_t wsrc[3];
#pragma unroll
    for (int i = 0; i < 3; ++i) {
        int idx = tid + NT * i;                // 0..1535
        int kqc = idx / 192, r2 = idx % 192;
        int kk = r2 / 12, r3 = r2 % 12;
        int g = r3 >> 2, c4 = r3 & 3;
        widx[i] = idx;
        wsrc[i] = (size_t)(kqc * 128 + kk) * G3 + g * HH + jbase + c4 * 4;
    }
    const unsigned int wst_su = smem_u32(wst);
    const unsigned int hsm_su = smem_u32(hsm);

    // gate-phase mapping: 1 output per thread
    const int gm = tid >> 4;                   // 0..31 local row
    const int gj = tid & 15;                   // 0..15 local col
    const int glocal = (gj >> 2) * 16 + (gm >> 1);
    const int gaidx = (gm & 1) * 12 + (gj & 3);

    const float* hrow0 = hsm + (2 * mp) * HP + kq * 128;
    const float* hrow1 = hrow0 + HP;

    u64t acc[12];

    for (int t = 0; t < SS; ++t) {
#pragma unroll
        for (int i = 0; i < 12; ++i) acc[i] = 0ULL;

        if (t > 0) {
            // stage h_{t-1} tile + W block 0 (one cp.async group)
            {
                const float* hbase = out + ((size_t)m0 * SS + (t - 1)) * HH;
#pragma unroll
                for (int i = 0; i < 16; ++i) {
                    int idx2 = tid + NT * i;           // 0..8191
                    int r = idx2 >> 8;
                    int c = (idx2 & 255) << 2;
                    cp16(hsm_su + (unsigned)(r * HP + c) * 4u,
                         hbase + (size_t)r * (SS * HH) + c);
                }
#pragma unroll
                for (int i = 0; i < 3; ++i)
                    cp16(wst_su + (unsigned)widx[i] * 16u, whh + wsrc[i]);
                cp_commit();
            }

#pragma unroll 1
            for (int rb = 0; rb < 8; ++rb) {
                if (rb < 7) {   // prefetch next W block into other buffer
                    unsigned int nb = ((rb + 1) & 1) ? (unsigned)WBUFB : 0u;
                    size_t soff = (size_t)(rb + 1) * 16 * G3;
#pragma unroll
                    for (int i = 0; i < 3; ++i)
                        cp16(wst_su + nb + (unsigned)widx[i] * 16u,
                             whh + wsrc[i] + soff);
                    cp_commit();
                    cp_wait<1>();
                } else {
                    cp_wait<0>();
                }
                __syncthreads();

                const float* wb = wst + ((rb & 1) ? 6144 : 0) + kq * 768 + jq * 4;
                const float* h0b = hrow0 + rb * 16;
                const float* h1b = hrow1 + rb * 16;
#pragma unroll
                for (int k4 = 0; k4 < 4; ++k4) {
                    float4 h0v = *(const float4*)(h0b + k4 * 4);
                    float4 h1v = *(const float4*)(h1b + k4 * 4);
                    float h0a[4] = {h0v.x, h0v.y, h0v.z, h0v.w};
                    float h1a[4] = {h1v.x, h1v.y, h1v.z, h1v.w};
#pragma unroll
                    for (int kk = 0; kk < 4; ++kk) {
                        const float* wp = wb + (k4 * 4 + kk) * 48;
                        ulonglong2 wz = *(const ulonglong2*)(wp);
                        ulonglong2 wr = *(const ulonglong2*)(wp + 16);
                        ulonglong2 we = *(const ulonglong2*)(wp + 32);
                        u64t h0p = pack2(h0a[kk], h0a[kk]);
                        u64t h1p = pack2(h1a[kk], h1a[kk]);
                        fma2(acc[0], h0p, wz.x);  fma2(acc[1], h0p, wz.y);
                        fma2(acc[2], h0p, wr.x);  fma2(acc[3], h0p, wr.y);
                        fma2(acc[4], h0p, we.x);  fma2(acc[5], h0p, we.y);
                        fma2(acc[6], h1p, wz.x);  fma2(acc[7], h1p, wz.y);
                        fma2(acc[8], h1p, wr.x);  fma2(acc[9], h1p, wr.y);
                        fma2(acc[10], h1p, we.x); fma2(acc[11], h1p, we.y);
                    }
                }
                __syncthreads();   // protects buffer reuse; last iter: before scratch
            }

            // dump partials to scratch (union with W buffers — W is dead now)
            {
                float* scr = wst + (kq * 64 + local) * SCR_STRIDE;
#pragma unroll
                for (int i = 0; i < 12; ++i)
                    *(u64t*)(scr + 2 * i) = acc[i];
            }
        }
        __syncthreads();

        // ---- gate phase: one output per thread ----
        {
            int mg = m0 + gm;
            const float* gp = g_gx + ((size_t)mg * SS + t) * G3 + jbase + gj;
            float gz = gp[0], gr = gp[HH], gev = gp[2 * HH];
            float sz = 0.0f, sr = 0.0f, se = 0.0f, hov = 0.0f;
            if (t > 0) {
#pragma unroll
                for (int q = 0; q < 8; ++q) {
                    const float* s = wst + (q * 64 + glocal) * SCR_STRIDE + gaidx;
                    sz += s[0];
                    sr += s[4];
                    se += s[8];
                }
                hov = hsm[gm * HP + jbase + gj];
            }
            float hn = gate_fn(gz + sz, gr + sr, gev, se, hov);
            out[((size_t)mg * SS + t) * HH + jbase + gj] = hn;
        }

        // ---- grid-wide barrier (release h_t to all CTAs) ----
        __threadfence();
        __syncthreads();
        if (tid == 0) {
            unsigned int my = g_gen;
            unsigned int old = atomicAdd(&g_count, 1u);
            if (old == NBLOCKS - 1) {
                atomicExch(&g_count, 0u);
                __threadfence();
                g_gen = my + 1u;
            } else {
                while (g_gen == my) { __nanosleep(32); }
            }
            __threadfence();
        }
        __syncthreads();
    }

    // h_last = hidden_seq[:, S-1, :]
    {
        int idx = bid * NT + tid;              // 0..65535
        int b = idx >> 10, j = idx & 1023;
        out[(size_t)BB * SS * HH + idx] =
            out[((size_t)b * SS + (SS - 1)) * HH + j];
    }
}

// ---------------------------------------------------------------------------
extern "C" void kernel_launch(void* const* d_in, const int* in_sizes, int n_in,
                              void* d_out, int out_size) {
    const float* x    = (const float*)d_in[0];  // [64,512,512]
    const float* wih  = (const float*)d_in[1];  // [512,3072]
    const float* whh  = (const float*)d_in[2];  // [1024,3072]
    const float* bias = (const float*)d_in[3];  // [3072]
    float* out = (float*)d_out;

    (void)in_sizes; (void)n_in; (void)out_size;

    dim3 g1(G3 / 128, (BB * SS) / 128);
    gemm_ih<<<g1, 256>>>(x, wih, bias);

    const int scan_smem = (32 * HP + 8 * 64 * SCR_STRIDE) * (int)sizeof(float); // 184832 B
    cudaFuncSetAttribute(gru_scan, cudaFuncAttributeMaxDynamicSharedMemorySize, scan_smem);
    gru_scan<<<NBLOCKS, NT, scan_smem>>>(whh, out);
}